// round 12
// baseline (speedup 1.0000x reference)
#include <cuda_runtime.h>
#include <cstdint>
#include <cstddef>

// ---------------- problem constants ----------------
constexpr int Bb   = 8;
constexpr int Ll   = 128;
constexpr int Dd   = 768;
constexpr int DEP  = 64;
constexpr int POSN = 64;
constexpr int OUTN = 768;
constexpr int BI   = Bb * Ll;                       // 1024 (b,i) rows
constexpr long long R_SIZE = (long long)BI * Ll * OUTN;   // 100663296
constexpr long long OS_OFF = R_SIZE;                       // output_sum offset
constexpr long long P_OFF  = R_SIZE + (long long)BI * OUTN; // p offset
#define NEGC (-1e30f)

// ---------------- scratch (device globals; no allocs) ----------------
__device__ __align__(16) float g_A[BI * OUTN];     // A[b,i,o]
__device__ __align__(16) float g_pd[BI * DEP];     // sum_j p * dep
__device__ float g_wt_sum[Dd];
__device__ float g_wp_sum[POSN];
__device__ float g_wd_sum[DEP];
__device__ float g_bias_out[OUTN];                 // bp + bd
__device__ float g_bsum;                           // sum(b_attn)

// ---------------- helpers ----------------
__device__ __forceinline__ float to_tf32(float x) {
    uint32_t u;
    asm("cvt.rna.tf32.f32 %0, %1;" : "=r"(u) : "f"(x));
    return __uint_as_float(u);
}
__device__ __forceinline__ void mma8(float c[4], const uint32_t a[4], const uint32_t b[2]) {
    asm volatile(
        "mma.sync.aligned.m16n8k8.row.col.f32.tf32.tf32.f32 "
        "{%0,%1,%2,%3},{%4,%5,%6,%7},{%8,%9},{%0,%1,%2,%3};\n"
        : "+f"(c[0]), "+f"(c[1]), "+f"(c[2]), "+f"(c[3])
        : "r"(a[0]), "r"(a[1]), "r"(a[2]), "r"(a[3]), "r"(b[0]), "r"(b[1]));
}

// ---------------- K0: row sums + combined bias (warp-per-row) ----------------
__global__ void k0_sums(const float* __restrict__ Wt, const float* __restrict__ Wpa,
                        const float* __restrict__ Wda, const float* __restrict__ b_attn,
                        const float* __restrict__ bd, const float* __restrict__ bp) {
    const int gw   = (blockIdx.x * blockDim.x + threadIdx.x) >> 5;
    const int lane = threadIdx.x & 31;
    if (gw <= 896) {
        const float* src;
        if (gw < 768)      src = Wt  + (size_t)gw * 768;
        else if (gw < 832) src = Wpa + (size_t)(gw - 768) * 768;
        else if (gw < 896) src = Wda + (size_t)(gw - 832) * 768;
        else               src = b_attn;
        const float4* p4 = (const float4*)src;
        float s = 0.f;
        #pragma unroll
        for (int i = 0; i < 6; i++) { float4 v = p4[lane + i * 32]; s += v.x + v.y + v.z + v.w; }
        #pragma unroll
        for (int o = 16; o; o >>= 1) s += __shfl_xor_sync(0xffffffffu, s, o);
        if (lane == 0) {
            if (gw < 768)      g_wt_sum[gw] = s;
            else if (gw < 832) g_wp_sum[gw - 768] = s;
            else if (gw < 896) g_wd_sum[gw - 832] = s;
            else               g_bsum = s;
        }
    } else if (gw >= 897 && gw < 921) {
        int n = (gw - 897) * 32 + lane;
        g_bias_out[n] = bp[n] + bd[n];
    }
}

// ---------------- gemm_A: A = text@Wt + pos@Wpa + ba  (pipelined, 8 warps) ----------------
// BM=64, BN=128, BK=32, grid (6,16)=96 CTAs, 256 thr (2x4 warps, warp tile 32x32).
// Register-prefetch double buffering of A and B chunks -> LDG latency hidden under mma.
// K order identical to the old gemm_small (text chunks then pos chunks) -> bitwise-same A.
__global__ void __launch_bounds__(256) gemm_A(
    const float* __restrict__ text, const float* __restrict__ pos,
    const float* __restrict__ Wt, const float* __restrict__ Wpa,
    const float* __restrict__ ba) {

    __shared__ float a_sm[64 * 36];
    __shared__ float b_sm[32 * 136];
    __shared__ float bias_s[128];

    const int tid   = threadIdx.x;
    const int nbase = blockIdx.x * 128;
    const int mbase = blockIdx.y * 64;

    if (tid < 128) bias_s[tid] = ba[nbase + tid];

    const int w  = tid >> 5, lane = tid & 31;
    const int g  = lane >> 2, t = lane & 3;
    const int wm = w >> 2, wn = w & 3;   // 2 x 4 warps

    float acc[2][4][4];
    #pragma unroll
    for (int mf = 0; mf < 2; mf++)
        #pragma unroll
        for (int nf = 0; nf < 4; nf++)
            #pragma unroll
            for (int q = 0; q < 4; q++) acc[mf][nf][q] = 0.f;

    float4 pfa[2], pfb[4];
    auto ldchunk = [&](int ch) {
        #pragma unroll
        for (int it = 0; it < 2; it++) {
            int idx = tid + it * 256;
            int row = idx >> 3, k4 = idx & 7;
            const float* src = (ch < 24)
                ? text + (size_t)(mbase + row) * 768 + ch * 32 + k4 * 4
                : pos  + (size_t)(mbase + row) * 64 + (ch - 24) * 32 + k4 * 4;
            pfa[it] = *(const float4*)src;
        }
        #pragma unroll
        for (int it = 0; it < 4; it++) {
            int idx = tid + it * 256;
            int kr = idx >> 5, c4 = idx & 31;
            const float* srcb = (ch < 24)
                ? Wt  + (size_t)(ch * 32 + kr) * 768 + nbase + c4 * 4
                : Wpa + (size_t)((ch - 24) * 32 + kr) * 768 + nbase + c4 * 4;
            pfb[it] = *(const float4*)srcb;
        }
    };
    ldchunk(0);

    for (int ch = 0; ch < 26; ch++) {
        __syncthreads();
        #pragma unroll
        for (int it = 0; it < 2; it++) {
            int idx = tid + it * 256;
            int row = idx >> 3, k4 = idx & 7;
            float4 v = pfa[it];
            *(float4*)(a_sm + row * 36 + k4 * 4) =
                make_float4(to_tf32(v.x), to_tf32(v.y), to_tf32(v.z), to_tf32(v.w));
        }
        #pragma unroll
        for (int it = 0; it < 4; it++) {
            int idx = tid + it * 256;
            int kr = idx >> 5, c4 = idx & 31;
            float4 v = pfb[it];
            *(float4*)(b_sm + kr * 136 + c4 * 4) =
                make_float4(to_tf32(v.x), to_tf32(v.y), to_tf32(v.z), to_tf32(v.w));
        }
        __syncthreads();
        if (ch + 1 < 26) ldchunk(ch + 1);

        #pragma unroll
        for (int ks = 0; ks < 4; ks++) {
            const int kb = ks * 8;
            uint32_t a[2][4], b[4][2];
            #pragma unroll
            for (int mf = 0; mf < 2; mf++) {
                int r = wm * 32 + mf * 16 + g;
                a[mf][0] = __float_as_uint(a_sm[r * 36 + kb + t]);
                a[mf][1] = __float_as_uint(a_sm[(r + 8) * 36 + kb + t]);
                a[mf][2] = __float_as_uint(a_sm[r * 36 + kb + 4 + t]);
                a[mf][3] = __float_as_uint(a_sm[(r + 8) * 36 + kb + 4 + t]);
            }
            #pragma unroll
            for (int nf = 0; nf < 4; nf++) {
                int c = wn * 32 + nf * 8 + g;
                b[nf][0] = __float_as_uint(b_sm[(kb + t) * 136 + c]);
                b[nf][1] = __float_as_uint(b_sm[(kb + 4 + t) * 136 + c]);
            }
            #pragma unroll
            for (int mf = 0; mf < 2; mf++)
                #pragma unroll
                for (int nf = 0; nf < 4; nf++) mma8(acc[mf][nf], a[mf], b[nf]);
        }
    }

    #pragma unroll
    for (int mf = 0; mf < 2; mf++) {
        #pragma unroll
        for (int nf = 0; nf < 4; nf++) {
            int r0 = mbase + wm * 32 + mf * 16 + g;
            int cl = wn * 32 + nf * 8 + 2 * t;
            int c  = nbase + cl;
            float2 v0 = make_float2(acc[mf][nf][0] + bias_s[cl], acc[mf][nf][1] + bias_s[cl + 1]);
            float2 v1 = make_float2(acc[mf][nf][2] + bias_s[cl], acc[mf][nf][3] + bias_s[cl + 1]);
            *(float2*)(g_A + (size_t)r0 * 768 + c) = v0;
            *(float2*)(g_A + (size_t)(r0 + 8) * 768 + c) = v1;
        }
    }
}

// ---------------- gemm_small (R6 version, used for output_sum): BM=64, BN=128, BK=32 ----------------
__global__ void __launch_bounds__(128) gemm_small(
    const float* __restrict__ A1, int lda1, const float* __restrict__ B1, int K1,
    const float* __restrict__ A2_, int lda2, const float* __restrict__ B2, int K2,
    int use_pd, const float* __restrict__ bias_, const float* __restrict__ addend,
    float* __restrict__ out_) {

    __shared__ float a_sm[64 * 36];
    __shared__ float b_sm[32 * 136];
    __shared__ float bias_s[128];

    const int tid   = threadIdx.x;
    const int nbase = blockIdx.x * 128;
    const int mbase = blockIdx.y * 64;
    const float* A2   = use_pd ? g_pd : A2_;
    float*       out  = out_ ? out_ : g_A;
    const float* bias = bias_ ? bias_ : g_bias_out;

    bias_s[tid] = bias[nbase + tid];

    const int w  = tid >> 5, lane = tid & 31;
    const int g  = lane >> 2, t = lane & 3;
    const int wm = w >> 1, wn = w & 1;

    float acc[2][8][4];
    #pragma unroll
    for (int mf = 0; mf < 2; mf++)
        #pragma unroll
        for (int nf = 0; nf < 8; nf++)
            #pragma unroll
            for (int q = 0; q < 4; q++) acc[mf][nf][q] = 0.f;

    #pragma unroll
    for (int s = 0; s < 2; s++) {
        const float* Ap = s ? A2 : A1;
        const float* Bp = s ? B2 : B1;
        const int lda   = s ? lda2 : lda1;
        const int Ks    = s ? K2 : K1;
        for (int kt = 0; kt < Ks; kt += 32) {
            #pragma unroll
            for (int it = 0; it < 4; it++) {
                int idx = tid + it * 128;
                int row = idx >> 3, k4 = idx & 7;
                float4 v = *(const float4*)(Ap + (size_t)(mbase + row) * lda + kt + k4 * 4);
                float4 wv = make_float4(to_tf32(v.x), to_tf32(v.y), to_tf32(v.z), to_tf32(v.w));
                *(float4*)(a_sm + row * 36 + k4 * 4) = wv;
            }
            #pragma unroll
            for (int it = 0; it < 8; it++) {
                int idx = tid + it * 128;
                int kr = idx >> 5, c4 = idx & 31;
                float4 v = *(const float4*)(Bp + (size_t)(kt + kr) * 768 + nbase + c4 * 4);
                float4 wv = make_float4(to_tf32(v.x), to_tf32(v.y), to_tf32(v.z), to_tf32(v.w));
                *(float4*)(b_sm + kr * 136 + c4 * 4) = wv;
            }
            __syncthreads();
            #pragma unroll
            for (int ks = 0; ks < 4; ks++) {
                const int kb = ks * 8;
                uint32_t a[2][4], b[8][2];
                #pragma unroll
                for (int mf = 0; mf < 2; mf++) {
                    int r = wm * 32 + mf * 16 + g;
                    a[mf][0] = __float_as_uint(a_sm[r * 36 + kb + t]);
                    a[mf][1] = __float_as_uint(a_sm[(r + 8) * 36 + kb + t]);
                    a[mf][2] = __float_as_uint(a_sm[r * 36 + kb + 4 + t]);
                    a[mf][3] = __float_as_uint(a_sm[(r + 8) * 36 + kb + 4 + t]);
                }
                #pragma unroll
                for (int nf = 0; nf < 8; nf++) {
                    int c = wn * 64 + nf * 8 + g;
                    b[nf][0] = __float_as_uint(b_sm[(kb + t) * 136 + c]);
                    b[nf][1] = __float_as_uint(b_sm[(kb + 4 + t) * 136 + c]);
                }
                #pragma unroll
                for (int mf = 0; mf < 2; mf++)
                    #pragma unroll
                    for (int nf = 0; nf < 8; nf++) mma8(acc[mf][nf], a[mf], b[nf]);
            }
            __syncthreads();
        }
    }

    #pragma unroll
    for (int mf = 0; mf < 2; mf++) {
        #pragma unroll
        for (int nf = 0; nf < 8; nf++) {
            int r0 = mbase + wm * 32 + mf * 16 + g;
            int cl = wn * 64 + nf * 8 + 2 * t;
            int c  = nbase + cl;
            float a0 = 0.f, a1 = 0.f, a2 = 0.f, a3 = 0.f;
            if (addend) {
                a0 = addend[(size_t)r0 * 768 + c];
                a1 = addend[(size_t)r0 * 768 + c + 1];
                a2 = addend[(size_t)(r0 + 8) * 768 + c];
                a3 = addend[(size_t)(r0 + 8) * 768 + c + 1];
            }
            float2 v0 = make_float2(acc[mf][nf][0] + bias_s[cl] + a0,
                                    acc[mf][nf][1] + bias_s[cl + 1] + a1);
            float2 v1 = make_float2(acc[mf][nf][2] + bias_s[cl] + a2,
                                    acc[mf][nf][3] + bias_s[cl + 1] + a3);
            *(float2*)(out + (size_t)r0 * 768 + c) = v0;
            *(float2*)(out + (size_t)(r0 + 8) * 768 + c) = v1;
        }
    }
}

// ---------------- kernel S: scores + softmax + p + p-weighted dep ----------------
__global__ void __launch_bounds__(128) kernel_s(
    const float* __restrict__ text, const int* __restrict__ adj,
    const float* __restrict__ dep, const float* __restrict__ pos,
    float* __restrict__ p_out) {

    __shared__ float dep_s[128 * 65];
    __shared__ float ws_s[64];
    __shared__ float p_s[128];
    __shared__ float red[128];

    const int bi  = blockIdx.x;
    const int tid = threadIdx.x;
    const int lane = tid & 31;

    if (tid < 64) ws_s[tid] = g_wd_sum[tid];

    float ps = 0.f;
    #pragma unroll
    for (int d = tid; d < 768; d += 128) ps += text[(size_t)bi * 768 + d] * g_wt_sum[d];
    if (tid < 64) ps += pos[(size_t)bi * 64 + tid] * g_wp_sum[tid];
    #pragma unroll
    for (int o = 16; o; o >>= 1) ps += __shfl_xor_sync(0xffffffffu, ps, o);
    if (lane == 0) red[tid >> 5] = ps;
    __syncthreads();
    const float s_base = red[0] + red[1] + red[2] + red[3] + g_bsum;
    __syncthreads();

    const float4* dr = (const float4*)(dep + ((size_t)bi * 128 + tid) * 64);
    float dot = 0.f;
    #pragma unroll
    for (int q = 0; q < 16; q++) {
        float4 v = dr[q];
        dot += v.x * ws_s[4 * q] + v.y * ws_s[4 * q + 1] + v.z * ws_s[4 * q + 2] + v.w * ws_s[4 * q + 3];
        int base = tid * 65 + 4 * q;
        dep_s[base]     = v.x;
        dep_s[base + 1] = v.y;
        dep_s[base + 2] = v.z;
        dep_s[base + 3] = v.w;
    }
    const float score = s_base + dot + (adj[(size_t)bi * 128 + tid] == 0 ? NEGC : 0.f);

    float m = score;
    #pragma unroll
    for (int o = 16; o; o >>= 1) m = fmaxf(m, __shfl_xor_sync(0xffffffffu, m, o));
    if (lane == 0) red[tid >> 5] = m;
    __syncthreads();
    const float mx = fmaxf(fmaxf(red[0], red[1]), fmaxf(red[2], red[3]));
    __syncthreads();
    const float e = expf(score - mx);
    float z = e;
    #pragma unroll
    for (int o = 16; o; o >>= 1) z += __shfl_xor_sync(0xffffffffu, z, o);
    if (lane == 0) red[tid >> 5] = z;
    __syncthreads();
    const float Z = red[0] + red[1] + red[2] + red[3];
    const float p = e / Z;
    p_s[tid] = p;
    p_out[(size_t)bi * 128 + tid] = p;
    __syncthreads();

    const int half = tid >> 6, k = tid & 63;
    float s = 0.f;
    #pragma unroll 4
    for (int j = half * 64; j < half * 64 + 64; j++) s += p_s[j] * dep_s[j * 65 + k];
    red[tid] = s;
    __syncthreads();
    if (tid < 64) g_pd[(size_t)bi * 64 + tid] = red[tid] + red[tid + 64];
}

// ---------------- kernel R: r = dep @ Wd_attn + A  (persistent; split-N stores) ----------------
constexpr int SD      = 68;                  // dep_s row stride (mod32==4)
constexpr int SBW     = 264;                 // wd_s row stride (mod32==8)
constexpr int R_DEPS  = 128 * SD;            // 8704 floats
constexpr int WDF     = 64 * SBW;            // 16896 floats
constexpr int R_SMEMB = (R_DEPS + WDF + 256) * 4;   // 103424 bytes
constexpr int NCH     = 49;

__global__ void __launch_bounds__(256, 1) kernel_r(
    const float* __restrict__ dep, const float* __restrict__ Wda,
    float* __restrict__ rout) {

    extern __shared__ float sm[];
    float* dep_s = sm;
    float* wd_s  = sm + R_DEPS;
    float* a_s   = wd_s + WDF;

    const int tid = threadIdx.x;
    const int nt  = blockIdx.x;   // 0..2 N-tile of 256 cols

    // ---- Wd_attn slice [64 x 256], column-permuted for STG.128 epilogue (once) ----
    #pragma unroll
    for (int it = 0; it < 16; it++) {
        int idx = tid + it * 256;
        int k = idx >> 6, c4 = idx & 63;
        float4 v = *(const float4*)(Wda + (size_t)k * 768 + nt * 256 + c4 * 4);
        int A  = c4 * 4;
        int L0 = (A & ~15) + (((A >> 2) & 3) << 1);
        *(float2*)(wd_s + k * SBW + L0)     = make_float2(to_tf32(v.x), to_tf32(v.y));
        *(float2*)(wd_s + k * SBW + L0 + 8) = make_float2(to_tf32(v.z), to_tf32(v.w));
    }

    const int w  = tid >> 5, lane = tid & 31;
    const int g  = lane >> 2, t = lane & 3;
    const int wm = w >> 2, wn = w & 3;   // 2 x 4 warps

    int bi = blockIdx.y;                 // strided by NCH

    float4 pf[8];
    float  pfa;
    {
        const float4* db4 = (const float4*)(dep + (size_t)bi * 8192);
        #pragma unroll
        for (int it = 0; it < 8; it++) pf[it] = db4[tid + it * 256];
        pfa = g_A[(size_t)bi * 768 + nt * 256 + tid];
    }

    while (true) {
        __syncthreads();
        #pragma unroll
        for (int it = 0; it < 8; it++) {
            int idx = tid + it * 256;
            int j = idx >> 4, k4 = idx & 15;
            float4 v = pf[it];
            *(float4*)(dep_s + j * SD + k4 * 4) =
                make_float4(to_tf32(v.x), to_tf32(v.y), to_tf32(v.z), to_tf32(v.w));
        }
        a_s[tid] = pfa;
        __syncthreads();

        const int bin = bi + NCH;
        if (bin < 1024) {
            const float4* db4 = (const float4*)(dep + (size_t)bin * 8192);
            #pragma unroll
            for (int it = 0; it < 8; it++) pf[it] = db4[tid + it * 256];
            pfa = g_A[(size_t)bin * 768 + nt * 256 + tid];
        }

        float* rbase = rout + (size_t)bi * 98304 + nt * 256;

        #pragma unroll
        for (int h = 0; h < 2; h++) {
            float acc[4][4][4];
            #pragma unroll
            for (int mf = 0; mf < 4; mf++)
                #pragma unroll
                for (int nf = 0; nf < 4; nf++)
                    #pragma unroll
                    for (int q = 0; q < 4; q++) acc[mf][nf][q] = 0.f;

            #pragma unroll
            for (int ks = 0; ks < 8; ks++) {
                const int kb = ks * 8;
                uint32_t a[4][4], b[4][2];
                #pragma unroll
                for (int mf = 0; mf < 4; mf++) {
                    int r = wm * 64 + mf * 16 + g;
                    a[mf][0] = __float_as_uint(dep_s[r * SD + kb + t]);
                    a[mf][1] = __float_as_uint(dep_s[(r + 8) * SD + kb + t]);
                    a[mf][2] = __float_as_uint(dep_s[r * SD + kb + 4 + t]);
                    a[mf][3] = __float_as_uint(dep_s[(r + 8) * SD + kb + 4 + t]);
                }
                #pragma unroll
                for (int nf = 0; nf < 4; nf++) {
                    int c = h * 128 + wn * 32 + nf * 8 + g;
                    b[nf][0] = __float_as_uint(wd_s[(kb + t) * SBW + c]);
                    b[nf][1] = __float_as_uint(wd_s[(kb + 4 + t) * SBW + c]);
                }
                #pragma unroll
                for (int mf = 0; mf < 4; mf++)
                    #pragma unroll
                    for (int nf = 0; nf < 4; nf++) mma8(acc[mf][nf], a[mf], b[nf]);
            }

            #pragma unroll
            for (int mf = 0; mf < 4; mf++) {
                #pragma unroll
                for (int q2 = 0; q2 < 2; q2++) {
                    int r0  = wm * 64 + mf * 16 + g;
                    int col = h * 128 + wn * 32 + (q2 << 4) + 4 * t;
                    float4 a4 = *(const float4*)(a_s + col);
                    float4 w0 = make_float4(acc[mf][2 * q2][0] + a4.x, acc[mf][2 * q2][1] + a4.y,
                                            acc[mf][2 * q2 + 1][0] + a4.z, acc[mf][2 * q2 + 1][1] + a4.w);
                    float4 w1 = make_float4(acc[mf][2 * q2][2] + a4.x, acc[mf][2 * q2][3] + a4.y,
                                            acc[mf][2 * q2 + 1][2] + a4.z, acc[mf][2 * q2 + 1][3] + a4.w);
                    __stcs((float4*)(rbase + (size_t)r0 * 768 + col), w0);
                    __stcs((float4*)(rbase + (size_t)(r0 + 8) * 768 + col), w1);
                }
            }
        }

        bi = bin;
        if (bi >= 1024) break;
    }
}

// ---------------- launch (fork/join; gemm2 at the end on main) ----------------
extern "C" void kernel_launch(void* const* d_in, const int* in_sizes, int n_in,
                              void* d_out, int out_size) {
    const float* text = (const float*)d_in[0];
    const int*   adj  = (const int*)d_in[1];
    const float* dep  = (const float*)d_in[2];
    const float* pos  = (const float*)d_in[3];
    const float* Wt   = (const float*)d_in[4];
    const float* Wpa  = (const float*)d_in[5];
    const float* Wda  = (const float*)d_in[6];
    const float* ba   = (const float*)d_in[7];
    const float* Wd   = (const float*)d_in[8];
    const float* bd   = (const float*)d_in[9];
    const float* Wp   = (const float*)d_in[10];
    const float* bp   = (const float*)d_in[11];
    float* out = (float*)d_out;

    // one-time resources (host-side only; no device memory)
    static cudaStream_t sB = nullptr;
    static cudaEvent_t  eF = nullptr, eS = nullptr;
    if (sB == nullptr) {
        cudaStreamCreateWithFlags(&sB, cudaStreamNonBlocking);
        cudaEventCreateWithFlags(&eF, cudaEventDisableTiming);
        cudaEventCreateWithFlags(&eS, cudaEventDisableTiming);
        cudaFuncSetAttribute(kernel_r, cudaFuncAttributeMaxDynamicSharedMemorySize, R_SMEMB);
    }

    // fork: side chain {k0 -> kernel_s} on sB (hides under gemm_A + kernel_r ramp)
    cudaEventRecord(eF, 0);
    cudaStreamWaitEvent(sB, eF, 0);
    k0_sums<<<116, 256, 0, sB>>>(Wt, Wpa, Wda, ba, bd, bp);
    kernel_s<<<BI, 128, 0, sB>>>(text, adj, dep, pos, out + P_OFF);
    cudaEventRecord(eS, sB);

    // main chain: gemm_A (fast) -> kernel_r
    gemm_A<<<dim3(6, 16), 256>>>(text, pos, Wt, Wpa, ba);
    kernel_r<<<dim3(3, NCH), 256, R_SMEMB>>>(dep, Wda, out);

    // gemm2 last, on the drained machine (needs g_pd + g_bias_out from side chain)
    cudaStreamWaitEvent(0, eS, 0);
    gemm_small<<<dim3(6, 16), 128>>>(pos, 64, Wp, 64, nullptr, 64, Wd, 64,
                                     /*use_pd=*/1, nullptr, text, out + OS_OFF);
}

// round 15
// speedup vs baseline: 1.3464x; 1.3464x over previous
#include <cuda_runtime.h>
#include <cstdint>
#include <cstddef>

// ---------------- problem constants ----------------
constexpr int Bb   = 8;
constexpr int Ll   = 128;
constexpr int Dd   = 768;
constexpr int DEP  = 64;
constexpr int POSN = 64;
constexpr int OUTN = 768;
constexpr int BI   = Bb * Ll;                       // 1024 (b,i) rows
constexpr long long R_SIZE = (long long)BI * Ll * OUTN;   // 100663296
constexpr long long OS_OFF = R_SIZE;                       // output_sum offset
constexpr long long P_OFF  = R_SIZE + (long long)BI * OUTN; // p offset
#define NEGC (-1e30f)

// ---------------- scratch (device globals; no allocs) ----------------
__device__ __align__(16) float g_A[BI * OUTN];     // A[b,i,o]
__device__ __align__(16) float g_pd[BI * DEP];     // sum_j p * dep
__device__ float g_wt_sum[Dd];
__device__ float g_wp_sum[POSN];
__device__ float g_wd_sum[DEP];
__device__ float g_bias_out[OUTN];                 // bp + bd
__device__ float g_bsum;                           // sum(b_attn)

// ---------------- helpers ----------------
__device__ __forceinline__ float to_tf32(float x) {
    uint32_t u;
    asm("cvt.rna.tf32.f32 %0, %1;" : "=r"(u) : "f"(x));
    return __uint_as_float(u);
}
__device__ __forceinline__ void mma8(float c[4], const uint32_t a[4], const uint32_t b[2]) {
    asm volatile(
        "mma.sync.aligned.m16n8k8.row.col.f32.tf32.tf32.f32 "
        "{%0,%1,%2,%3},{%4,%5,%6,%7},{%8,%9},{%0,%1,%2,%3};\n"
        : "+f"(c[0]), "+f"(c[1]), "+f"(c[2]), "+f"(c[3])
        : "r"(a[0]), "r"(a[1]), "r"(a[2]), "r"(a[3]), "r"(b[0]), "r"(b[1]));
}

// ---------------- K0: row sums + combined bias (warp-per-row) ----------------
__global__ void k0_sums(const float* __restrict__ Wt, const float* __restrict__ Wpa,
                        const float* __restrict__ Wda, const float* __restrict__ b_attn,
                        const float* __restrict__ bd, const float* __restrict__ bp) {
    const int gw   = (blockIdx.x * blockDim.x + threadIdx.x) >> 5;
    const int lane = threadIdx.x & 31;
    if (gw <= 896) {
        const float* src;
        if (gw < 768)      src = Wt  + (size_t)gw * 768;
        else if (gw < 832) src = Wpa + (size_t)(gw - 768) * 768;
        else if (gw < 896) src = Wda + (size_t)(gw - 832) * 768;
        else               src = b_attn;
        const float4* p4 = (const float4*)src;
        float s = 0.f;
        #pragma unroll
        for (int i = 0; i < 6; i++) { float4 v = p4[lane + i * 32]; s += v.x + v.y + v.z + v.w; }
        #pragma unroll
        for (int o = 16; o; o >>= 1) s += __shfl_xor_sync(0xffffffffu, s, o);
        if (lane == 0) {
            if (gw < 768)      g_wt_sum[gw] = s;
            else if (gw < 832) g_wp_sum[gw - 768] = s;
            else if (gw < 896) g_wd_sum[gw - 832] = s;
            else               g_bsum = s;
        }
    } else if (gw >= 897 && gw < 921) {
        int n = (gw - 897) * 32 + lane;
        g_bias_out[n] = bp[n] + bd[n];
    }
}

// ---------------- gemm_A: A = text@Wt + pos@Wpa + ba  (pipelined, 8 warps) ----------------
// BM=64, BN=128, BK=32, grid (6,16)=96 CTAs, 256 thr (2x4 warps, warp tile 32x32).
// Register-prefetch double buffering of A and B chunks -> LDG latency hidden under mma.
// K order identical to the old gemm_small (text chunks then pos chunks) -> bitwise-same A.
__global__ void __launch_bounds__(256) gemm_A(
    const float* __restrict__ text, const float* __restrict__ pos,
    const float* __restrict__ Wt, const float* __restrict__ Wpa,
    const float* __restrict__ ba) {

    __shared__ float a_sm[64 * 36];
    __shared__ float b_sm[32 * 136];
    __shared__ float bias_s[128];

    const int tid   = threadIdx.x;
    const int nbase = blockIdx.x * 128;
    const int mbase = blockIdx.y * 64;

    if (tid < 128) bias_s[tid] = ba[nbase + tid];

    const int w  = tid >> 5, lane = tid & 31;
    const int g  = lane >> 2, t = lane & 3;
    const int wm = w >> 2, wn = w & 3;   // 2 x 4 warps

    float acc[2][4][4];
    #pragma unroll
    for (int mf = 0; mf < 2; mf++)
        #pragma unroll
        for (int nf = 0; nf < 4; nf++)
            #pragma unroll
            for (int q = 0; q < 4; q++) acc[mf][nf][q] = 0.f;

    float4 pfa[2], pfb[4];
    auto ldchunk = [&](int ch) {
        #pragma unroll
        for (int it = 0; it < 2; it++) {
            int idx = tid + it * 256;
            int row = idx >> 3, k4 = idx & 7;
            const float* src = (ch < 24)
                ? text + (size_t)(mbase + row) * 768 + ch * 32 + k4 * 4
                : pos  + (size_t)(mbase + row) * 64 + (ch - 24) * 32 + k4 * 4;
            pfa[it] = *(const float4*)src;
        }
        #pragma unroll
        for (int it = 0; it < 4; it++) {
            int idx = tid + it * 256;
            int kr = idx >> 5, c4 = idx & 31;
            const float* srcb = (ch < 24)
                ? Wt  + (size_t)(ch * 32 + kr) * 768 + nbase + c4 * 4
                : Wpa + (size_t)((ch - 24) * 32 + kr) * 768 + nbase + c4 * 4;
            pfb[it] = *(const float4*)srcb;
        }
    };
    ldchunk(0);

    for (int ch = 0; ch < 26; ch++) {
        __syncthreads();
        #pragma unroll
        for (int it = 0; it < 2; it++) {
            int idx = tid + it * 256;
            int row = idx >> 3, k4 = idx & 7;
            float4 v = pfa[it];
            *(float4*)(a_sm + row * 36 + k4 * 4) =
                make_float4(to_tf32(v.x), to_tf32(v.y), to_tf32(v.z), to_tf32(v.w));
        }
        #pragma unroll
        for (int it = 0; it < 4; it++) {
            int idx = tid + it * 256;
            int kr = idx >> 5, c4 = idx & 31;
            float4 v = pfb[it];
            *(float4*)(b_sm + kr * 136 + c4 * 4) =
                make_float4(to_tf32(v.x), to_tf32(v.y), to_tf32(v.z), to_tf32(v.w));
        }
        __syncthreads();
        if (ch + 1 < 26) ldchunk(ch + 1);

        #pragma unroll
        for (int ks = 0; ks < 4; ks++) {
            const int kb = ks * 8;
            uint32_t a[2][4], b[4][2];
            #pragma unroll
            for (int mf = 0; mf < 2; mf++) {
                int r = wm * 32 + mf * 16 + g;
                a[mf][0] = __float_as_uint(a_sm[r * 36 + kb + t]);
                a[mf][1] = __float_as_uint(a_sm[(r + 8) * 36 + kb + t]);
                a[mf][2] = __float_as_uint(a_sm[r * 36 + kb + 4 + t]);
                a[mf][3] = __float_as_uint(a_sm[(r + 8) * 36 + kb + 4 + t]);
            }
            #pragma unroll
            for (int nf = 0; nf < 4; nf++) {
                int c = wn * 32 + nf * 8 + g;
                b[nf][0] = __float_as_uint(b_sm[(kb + t) * 136 + c]);
                b[nf][1] = __float_as_uint(b_sm[(kb + 4 + t) * 136 + c]);
            }
            #pragma unroll
            for (int mf = 0; mf < 2; mf++)
                #pragma unroll
                for (int nf = 0; nf < 4; nf++) mma8(acc[mf][nf], a[mf], b[nf]);
        }
    }

    #pragma unroll
    for (int mf = 0; mf < 2; mf++) {
        #pragma unroll
        for (int nf = 0; nf < 4; nf++) {
            int r0 = mbase + wm * 32 + mf * 16 + g;
            int cl = wn * 32 + nf * 8 + 2 * t;
            int c  = nbase + cl;
            float2 v0 = make_float2(acc[mf][nf][0] + bias_s[cl], acc[mf][nf][1] + bias_s[cl + 1]);
            float2 v1 = make_float2(acc[mf][nf][2] + bias_s[cl], acc[mf][nf][3] + bias_s[cl + 1]);
            *(float2*)(g_A + (size_t)r0 * 768 + c) = v0;
            *(float2*)(g_A + (size_t)(r0 + 8) * 768 + c) = v1;
        }
    }
}

// ---------------- gemm_small (R6 version, used for output_sum): BM=64, BN=128, BK=32 ----------------
__global__ void __launch_bounds__(128) gemm_small(
    const float* __restrict__ A1, int lda1, const float* __restrict__ B1, int K1,
    const float* __restrict__ A2_, int lda2, const float* __restrict__ B2, int K2,
    int use_pd, const float* __restrict__ bias_, const float* __restrict__ addend,
    float* __restrict__ out_) {

    __shared__ float a_sm[64 * 36];
    __shared__ float b_sm[32 * 136];
    __shared__ float bias_s[128];

    const int tid   = threadIdx.x;
    const int nbase = blockIdx.x * 128;
    const int mbase = blockIdx.y * 64;
    const float* A2   = use_pd ? g_pd : A2_;
    float*       out  = out_ ? out_ : g_A;
    const float* bias = bias_ ? bias_ : g_bias_out;

    bias_s[tid] = bias[nbase + tid];

    const int w  = tid >> 5, lane = tid & 31;
    const int g  = lane >> 2, t = lane & 3;
    const int wm = w >> 1, wn = w & 1;

    float acc[2][8][4];
    #pragma unroll
    for (int mf = 0; mf < 2; mf++)
        #pragma unroll
        for (int nf = 0; nf < 8; nf++)
            #pragma unroll
            for (int q = 0; q < 4; q++) acc[mf][nf][q] = 0.f;

    #pragma unroll
    for (int s = 0; s < 2; s++) {
        const float* Ap = s ? A2 : A1;
        const float* Bp = s ? B2 : B1;
        const int lda   = s ? lda2 : lda1;
        const int Ks    = s ? K2 : K1;
        for (int kt = 0; kt < Ks; kt += 32) {
            #pragma unroll
            for (int it = 0; it < 4; it++) {
                int idx = tid + it * 128;
                int row = idx >> 3, k4 = idx & 7;
                float4 v = *(const float4*)(Ap + (size_t)(mbase + row) * lda + kt + k4 * 4);
                float4 wv = make_float4(to_tf32(v.x), to_tf32(v.y), to_tf32(v.z), to_tf32(v.w));
                *(float4*)(a_sm + row * 36 + k4 * 4) = wv;
            }
            #pragma unroll
            for (int it = 0; it < 8; it++) {
                int idx = tid + it * 128;
                int kr = idx >> 5, c4 = idx & 31;
                float4 v = *(const float4*)(Bp + (size_t)(kt + kr) * 768 + nbase + c4 * 4);
                float4 wv = make_float4(to_tf32(v.x), to_tf32(v.y), to_tf32(v.z), to_tf32(v.w));
                *(float4*)(b_sm + kr * 136 + c4 * 4) = wv;
            }
            __syncthreads();
            #pragma unroll
            for (int ks = 0; ks < 4; ks++) {
                const int kb = ks * 8;
                uint32_t a[2][4], b[8][2];
                #pragma unroll
                for (int mf = 0; mf < 2; mf++) {
                    int r = wm * 32 + mf * 16 + g;
                    a[mf][0] = __float_as_uint(a_sm[r * 36 + kb + t]);
                    a[mf][1] = __float_as_uint(a_sm[(r + 8) * 36 + kb + t]);
                    a[mf][2] = __float_as_uint(a_sm[r * 36 + kb + 4 + t]);
                    a[mf][3] = __float_as_uint(a_sm[(r + 8) * 36 + kb + 4 + t]);
                }
                #pragma unroll
                for (int nf = 0; nf < 8; nf++) {
                    int c = wn * 64 + nf * 8 + g;
                    b[nf][0] = __float_as_uint(b_sm[(kb + t) * 136 + c]);
                    b[nf][1] = __float_as_uint(b_sm[(kb + 4 + t) * 136 + c]);
                }
                #pragma unroll
                for (int mf = 0; mf < 2; mf++)
                    #pragma unroll
                    for (int nf = 0; nf < 8; nf++) mma8(acc[mf][nf], a[mf], b[nf]);
            }
            __syncthreads();
        }
    }

    #pragma unroll
    for (int mf = 0; mf < 2; mf++) {
        #pragma unroll
        for (int nf = 0; nf < 8; nf++) {
            int r0 = mbase + wm * 32 + mf * 16 + g;
            int cl = wn * 64 + nf * 8 + 2 * t;
            int c  = nbase + cl;
            float a0 = 0.f, a1 = 0.f, a2 = 0.f, a3 = 0.f;
            if (addend) {
                a0 = addend[(size_t)r0 * 768 + c];
                a1 = addend[(size_t)r0 * 768 + c + 1];
                a2 = addend[(size_t)(r0 + 8) * 768 + c];
                a3 = addend[(size_t)(r0 + 8) * 768 + c + 1];
            }
            float2 v0 = make_float2(acc[mf][nf][0] + bias_s[cl] + a0,
                                    acc[mf][nf][1] + bias_s[cl + 1] + a1);
            float2 v1 = make_float2(acc[mf][nf][2] + bias_s[cl] + a2,
                                    acc[mf][nf][3] + bias_s[cl + 1] + a3);
            *(float2*)(out + (size_t)r0 * 768 + c) = v0;
            *(float2*)(out + (size_t)(r0 + 8) * 768 + c) = v1;
        }
    }
}

// ---------------- kernel S: scores + softmax + p + p-weighted dep ----------------
__global__ void __launch_bounds__(128) kernel_s(
    const float* __restrict__ text, const int* __restrict__ adj,
    const float* __restrict__ dep, const float* __restrict__ pos,
    float* __restrict__ p_out) {

    __shared__ float dep_s[128 * 65];
    __shared__ float ws_s[64];
    __shared__ float p_s[128];
    __shared__ float red[128];

    const int bi  = blockIdx.x;
    const int tid = threadIdx.x;
    const int lane = tid & 31;

    if (tid < 64) ws_s[tid] = g_wd_sum[tid];

    float ps = 0.f;
    #pragma unroll
    for (int d = tid; d < 768; d += 128) ps += text[(size_t)bi * 768 + d] * g_wt_sum[d];
    if (tid < 64) ps += pos[(size_t)bi * 64 + tid] * g_wp_sum[tid];
    #pragma unroll
    for (int o = 16; o; o >>= 1) ps += __shfl_xor_sync(0xffffffffu, ps, o);
    if (lane == 0) red[tid >> 5] = ps;
    __syncthreads();
    const float s_base = red[0] + red[1] + red[2] + red[3] + g_bsum;
    __syncthreads();

    const float4* dr = (const float4*)(dep + ((size_t)bi * 128 + tid) * 64);
    float dot = 0.f;
    #pragma unroll
    for (int q = 0; q < 16; q++) {
        float4 v = dr[q];
        dot += v.x * ws_s[4 * q] + v.y * ws_s[4 * q + 1] + v.z * ws_s[4 * q + 2] + v.w * ws_s[4 * q + 3];
        int base = tid * 65 + 4 * q;
        dep_s[base]     = v.x;
        dep_s[base + 1] = v.y;
        dep_s[base + 2] = v.z;
        dep_s[base + 3] = v.w;
    }
    const float score = s_base + dot + (adj[(size_t)bi * 128 + tid] == 0 ? NEGC : 0.f);

    float m = score;
    #pragma unroll
    for (int o = 16; o; o >>= 1) m = fmaxf(m, __shfl_xor_sync(0xffffffffu, m, o));
    if (lane == 0) red[tid >> 5] = m;
    __syncthreads();
    const float mx = fmaxf(fmaxf(red[0], red[1]), fmaxf(red[2], red[3]));
    __syncthreads();
    const float e = expf(score - mx);
    float z = e;
    #pragma unroll
    for (int o = 16; o; o >>= 1) z += __shfl_xor_sync(0xffffffffu, z, o);
    if (lane == 0) red[tid >> 5] = z;
    __syncthreads();
    const float Z = red[0] + red[1] + red[2] + red[3];
    const float p = e / Z;
    p_s[tid] = p;
    p_out[(size_t)bi * 128 + tid] = p;
    __syncthreads();

    const int half = tid >> 6, k = tid & 63;
    float s = 0.f;
    #pragma unroll 4
    for (int j = half * 64; j < half * 64 + 64; j++) s += p_s[j] * dep_s[j * 65 + k];
    red[tid] = s;
    __syncthreads();
    if (tid < 64) g_pd[(size_t)bi * 64 + tid] = red[tid] + red[tid + 64];
}

// ---------------- kernel R: r = dep @ Wd_attn + A  (persistent; split-N stores) ----------------
constexpr int SD      = 68;                  // dep_s row stride (mod32==4)
constexpr int SBW     = 264;                 // wd_s row stride (mod32==8)
constexpr int R_DEPS  = 128 * SD;            // 8704 floats
constexpr int WDF     = 64 * SBW;            // 16896 floats
constexpr int R_SMEMB = (R_DEPS + WDF + 256) * 4;   // 103424 bytes
constexpr int NCH     = 49;

__global__ void __launch_bounds__(256, 1) kernel_r(
    const float* __restrict__ dep, const float* __restrict__ Wda,
    float* __restrict__ rout) {

    extern __shared__ float sm[];
    float* dep_s = sm;
    float* wd_s  = sm + R_DEPS;
    float* a_s   = wd_s + WDF;

    const int tid = threadIdx.x;
    const int nt  = blockIdx.x;   // 0..2 N-tile of 256 cols

    // ---- Wd_attn slice [64 x 256], column-permuted for STG.128 epilogue (once) ----
    #pragma unroll
    for (int it = 0; it < 16; it++) {
        int idx = tid + it * 256;
        int k = idx >> 6, c4 = idx & 63;
        float4 v = *(const float4*)(Wda + (size_t)k * 768 + nt * 256 + c4 * 4);
        int A  = c4 * 4;
        int L0 = (A & ~15) + (((A >> 2) & 3) << 1);
        *(float2*)(wd_s + k * SBW + L0)     = make_float2(to_tf32(v.x), to_tf32(v.y));
        *(float2*)(wd_s + k * SBW + L0 + 8) = make_float2(to_tf32(v.z), to_tf32(v.w));
    }

    const int w  = tid >> 5, lane = tid & 31;
    const int g  = lane >> 2, t = lane & 3;
    const int wm = w >> 2, wn = w & 3;   // 2 x 4 warps

    int bi = blockIdx.y;                 // strided by NCH

    float4 pf[8];
    float  pfa;
    {
        const float4* db4 = (const float4*)(dep + (size_t)bi * 8192);
        #pragma unroll
        for (int it = 0; it < 8; it++) pf[it] = db4[tid + it * 256];
        pfa = g_A[(size_t)bi * 768 + nt * 256 + tid];
    }

    while (true) {
        __syncthreads();
        #pragma unroll
        for (int it = 0; it < 8; it++) {
            int idx = tid + it * 256;
            int j = idx >> 4, k4 = idx & 15;
            float4 v = pf[it];
            *(float4*)(dep_s + j * SD + k4 * 4) =
                make_float4(to_tf32(v.x), to_tf32(v.y), to_tf32(v.z), to_tf32(v.w));
        }
        a_s[tid] = pfa;
        __syncthreads();

        const int bin = bi + NCH;
        if (bin < 1024) {
            const float4* db4 = (const float4*)(dep + (size_t)bin * 8192);
            #pragma unroll
            for (int it = 0; it < 8; it++) pf[it] = db4[tid + it * 256];
            pfa = g_A[(size_t)bin * 768 + nt * 256 + tid];
        }

        float* rbase = rout + (size_t)bi * 98304 + nt * 256;

        #pragma unroll
        for (int h = 0; h < 2; h++) {
            float acc[4][4][4];
            #pragma unroll
            for (int mf = 0; mf < 4; mf++)
                #pragma unroll
                for (int nf = 0; nf < 4; nf++)
                    #pragma unroll
                    for (int q = 0; q < 4; q++) acc[mf][nf][q] = 0.f;

            #pragma unroll
            for (int ks = 0; ks < 8; ks++) {
                const int kb = ks * 8;
                uint32_t a[4][4], b[4][2];
                #pragma unroll
                for (int mf = 0; mf < 4; mf++) {
                    int r = wm * 64 + mf * 16 + g;
                    a[mf][0] = __float_as_uint(dep_s[r * SD + kb + t]);
                    a[mf][1] = __float_as_uint(dep_s[(r + 8) * SD + kb + t]);
                    a[mf][2] = __float_as_uint(dep_s[r * SD + kb + 4 + t]);
                    a[mf][3] = __float_as_uint(dep_s[(r + 8) * SD + kb + 4 + t]);
                }
                #pragma unroll
                for (int nf = 0; nf < 4; nf++) {
                    int c = h * 128 + wn * 32 + nf * 8 + g;
                    b[nf][0] = __float_as_uint(wd_s[(kb + t) * SBW + c]);
                    b[nf][1] = __float_as_uint(wd_s[(kb + 4 + t) * SBW + c]);
                }
                #pragma unroll
                for (int mf = 0; mf < 4; mf++)
                    #pragma unroll
                    for (int nf = 0; nf < 4; nf++) mma8(acc[mf][nf], a[mf], b[nf]);
            }

            #pragma unroll
            for (int mf = 0; mf < 4; mf++) {
                #pragma unroll
                for (int q2 = 0; q2 < 2; q2++) {
                    int r0  = wm * 64 + mf * 16 + g;
                    int col = h * 128 + wn * 32 + (q2 << 4) + 4 * t;
                    float4 a4 = *(const float4*)(a_s + col);
                    float4 w0 = make_float4(acc[mf][2 * q2][0] + a4.x, acc[mf][2 * q2][1] + a4.y,
                                            acc[mf][2 * q2 + 1][0] + a4.z, acc[mf][2 * q2 + 1][1] + a4.w);
                    float4 w1 = make_float4(acc[mf][2 * q2][2] + a4.x, acc[mf][2 * q2][3] + a4.y,
                                            acc[mf][2 * q2 + 1][2] + a4.z, acc[mf][2 * q2 + 1][3] + a4.w);
                    __stcs((float4*)(rbase + (size_t)r0 * 768 + col), w0);
                    __stcs((float4*)(rbase + (size_t)(r0 + 8) * 768 + col), w1);
                }
            }
        }

        bi = bin;
        if (bi >= 1024) break;
    }
}

// ---------------- launch: side chain fully joins BEFORE kernel_r (exclusive chip) ----------------
extern "C" void kernel_launch(void* const* d_in, const int* in_sizes, int n_in,
                              void* d_out, int out_size) {
    const float* text = (const float*)d_in[0];
    const int*   adj  = (const int*)d_in[1];
    const float* dep  = (const float*)d_in[2];
    const float* pos  = (const float*)d_in[3];
    const float* Wt   = (const float*)d_in[4];
    const float* Wpa  = (const float*)d_in[5];
    const float* Wda  = (const float*)d_in[6];
    const float* ba   = (const float*)d_in[7];
    const float* Wd   = (const float*)d_in[8];
    const float* bd   = (const float*)d_in[9];
    const float* Wp   = (const float*)d_in[10];
    const float* bp   = (const float*)d_in[11];
    float* out = (float*)d_out;

    // one-time resources (host-side only; no device memory)
    static cudaStream_t sB = nullptr;
    static cudaEvent_t  eF = nullptr, eS = nullptr;
    if (sB == nullptr) {
        cudaStreamCreateWithFlags(&sB, cudaStreamNonBlocking);
        cudaEventCreateWithFlags(&eF, cudaEventDisableTiming);
        cudaEventCreateWithFlags(&eS, cudaEventDisableTiming);
        cudaFuncSetAttribute(kernel_r, cudaFuncAttributeMaxDynamicSharedMemorySize, R_SMEMB);
    }

    // fork: side chain {k0 -> kernel_s} on sB, concurrent with gemm_A on main
    cudaEventRecord(eF, 0);
    cudaStreamWaitEvent(sB, eF, 0);
    k0_sums<<<116, 256, 0, sB>>>(Wt, Wpa, Wda, ba, bd, bp);
    kernel_s<<<BI, 128, 0, sB>>>(text, adj, dep, pos, out + P_OFF);
    cudaEventRecord(eS, sB);

    // main: gemm_A runs concurrently with the side chain
    gemm_A<<<dim3(6, 16), 256>>>(text, pos, Wt, Wpa, ba);

    // JOIN before kernel_r: the persistent one-wave kernel must own the whole chip
    cudaStreamWaitEvent(0, eS, 0);
    kernel_r<<<dim3(3, NCH), 256, R_SMEMB>>>(dep, Wda, out);

    // gemm2 last, on the drained machine
    gemm_small<<<dim3(6, 16), 128>>>(pos, 64, Wp, 64, nullptr, 64, Wd, 64,
                                     /*use_pd=*/1, nullptr, text, out + OS_OFF);
}

// round 16
// speedup vs baseline: 1.4103x; 1.0475x over previous
#include <cuda_runtime.h>
#include <cstdint>
#include <cstddef>

// ---------------- problem constants ----------------
constexpr int Bb   = 8;
constexpr int Ll   = 128;
constexpr int Dd   = 768;
constexpr int DEP  = 64;
constexpr int POSN = 64;
constexpr int OUTN = 768;
constexpr int BI   = Bb * Ll;                       // 1024 (b,i) rows
constexpr long long R_SIZE = (long long)BI * Ll * OUTN;   // 100663296
constexpr long long OS_OFF = R_SIZE;                       // output_sum offset
constexpr long long P_OFF  = R_SIZE + (long long)BI * OUTN; // p offset
#define NEGC (-1e30f)

// ---------------- scratch (device globals; no allocs) ----------------
__device__ __align__(16) float g_A[BI * OUTN];     // A[b,i,o]
__device__ __align__(16) float g_pd[BI * DEP];     // sum_j p * dep
__device__ float g_wt_sum[Dd];
__device__ float g_wp_sum[POSN];
__device__ float g_wd_sum[DEP];
__device__ float g_bias_out[OUTN];                 // bp + bd
__device__ float g_bsum;                           // sum(b_attn)

// ---------------- helpers ----------------
__device__ __forceinline__ float to_tf32(float x) {
    uint32_t u;
    asm("cvt.rna.tf32.f32 %0, %1;" : "=r"(u) : "f"(x));
    return __uint_as_float(u);
}
__device__ __forceinline__ void mma8(float c[4], const uint32_t a[4], const uint32_t b[2]) {
    asm volatile(
        "mma.sync.aligned.m16n8k8.row.col.f32.tf32.tf32.f32 "
        "{%0,%1,%2,%3},{%4,%5,%6,%7},{%8,%9},{%0,%1,%2,%3};\n"
        : "+f"(c[0]), "+f"(c[1]), "+f"(c[2]), "+f"(c[3])
        : "r"(a[0]), "r"(a[1]), "r"(a[2]), "r"(a[3]), "r"(b[0]), "r"(b[1]));
}

// ---------------- K0: row sums + combined bias (warp-per-row) ----------------
__global__ void k0_sums(const float* __restrict__ Wt, const float* __restrict__ Wpa,
                        const float* __restrict__ Wda, const float* __restrict__ b_attn,
                        const float* __restrict__ bd, const float* __restrict__ bp) {
    const int gw   = (blockIdx.x * blockDim.x + threadIdx.x) >> 5;
    const int lane = threadIdx.x & 31;
    if (gw <= 896) {
        const float* src;
        if (gw < 768)      src = Wt  + (size_t)gw * 768;
        else if (gw < 832) src = Wpa + (size_t)(gw - 768) * 768;
        else if (gw < 896) src = Wda + (size_t)(gw - 832) * 768;
        else               src = b_attn;
        const float4* p4 = (const float4*)src;
        float s = 0.f;
        #pragma unroll
        for (int i = 0; i < 6; i++) { float4 v = p4[lane + i * 32]; s += v.x + v.y + v.z + v.w; }
        #pragma unroll
        for (int o = 16; o; o >>= 1) s += __shfl_xor_sync(0xffffffffu, s, o);
        if (lane == 0) {
            if (gw < 768)      g_wt_sum[gw] = s;
            else if (gw < 832) g_wp_sum[gw - 768] = s;
            else if (gw < 896) g_wd_sum[gw - 832] = s;
            else               g_bsum = s;
        }
    } else if (gw >= 897 && gw < 921) {
        int n = (gw - 897) * 32 + lane;
        g_bias_out[n] = bp[n] + bd[n];
    }
}

// ---------------- gemm_A: A = text@Wt + pos@Wpa + ba  (pipelined, 8 warps) ----------------
// BM=64, BN=128, BK=32, grid (6,16)=96 CTAs, 256 thr (2x4 warps, warp tile 32x32).
// Register-prefetch double buffering; K order matches original -> bitwise-same A.
__global__ void __launch_bounds__(256) gemm_A(
    const float* __restrict__ text, const float* __restrict__ pos,
    const float* __restrict__ Wt, const float* __restrict__ Wpa,
    const float* __restrict__ ba) {

    __shared__ float a_sm[64 * 36];
    __shared__ float b_sm[32 * 136];
    __shared__ float bias_s[128];

    const int tid   = threadIdx.x;
    const int nbase = blockIdx.x * 128;
    const int mbase = blockIdx.y * 64;

    if (tid < 128) bias_s[tid] = ba[nbase + tid];

    const int w  = tid >> 5, lane = tid & 31;
    const int g  = lane >> 2, t = lane & 3;
    const int wm = w >> 2, wn = w & 3;   // 2 x 4 warps

    float acc[2][4][4];
    #pragma unroll
    for (int mf = 0; mf < 2; mf++)
        #pragma unroll
        for (int nf = 0; nf < 4; nf++)
            #pragma unroll
            for (int q = 0; q < 4; q++) acc[mf][nf][q] = 0.f;

    float4 pfa[2], pfb[4];
    auto ldchunk = [&](int ch) {
        #pragma unroll
        for (int it = 0; it < 2; it++) {
            int idx = tid + it * 256;
            int row = idx >> 3, k4 = idx & 7;
            const float* src = (ch < 24)
                ? text + (size_t)(mbase + row) * 768 + ch * 32 + k4 * 4
                : pos  + (size_t)(mbase + row) * 64 + (ch - 24) * 32 + k4 * 4;
            pfa[it] = *(const float4*)src;
        }
        #pragma unroll
        for (int it = 0; it < 4; it++) {
            int idx = tid + it * 256;
            int kr = idx >> 5, c4 = idx & 31;
            const float* srcb = (ch < 24)
                ? Wt  + (size_t)(ch * 32 + kr) * 768 + nbase + c4 * 4
                : Wpa + (size_t)((ch - 24) * 32 + kr) * 768 + nbase + c4 * 4;
            pfb[it] = *(const float4*)srcb;
        }
    };
    ldchunk(0);

    for (int ch = 0; ch < 26; ch++) {
        __syncthreads();
        #pragma unroll
        for (int it = 0; it < 2; it++) {
            int idx = tid + it * 256;
            int row = idx >> 3, k4 = idx & 7;
            float4 v = pfa[it];
            *(float4*)(a_sm + row * 36 + k4 * 4) =
                make_float4(to_tf32(v.x), to_tf32(v.y), to_tf32(v.z), to_tf32(v.w));
        }
        #pragma unroll
        for (int it = 0; it < 4; it++) {
            int idx = tid + it * 256;
            int kr = idx >> 5, c4 = idx & 31;
            float4 v = pfb[it];
            *(float4*)(b_sm + kr * 136 + c4 * 4) =
                make_float4(to_tf32(v.x), to_tf32(v.y), to_tf32(v.z), to_tf32(v.w));
        }
        __syncthreads();
        if (ch + 1 < 26) ldchunk(ch + 1);

        #pragma unroll
        for (int ks = 0; ks < 4; ks++) {
            const int kb = ks * 8;
            uint32_t a[2][4], b[4][2];
            #pragma unroll
            for (int mf = 0; mf < 2; mf++) {
                int r = wm * 32 + mf * 16 + g;
                a[mf][0] = __float_as_uint(a_sm[r * 36 + kb + t]);
                a[mf][1] = __float_as_uint(a_sm[(r + 8) * 36 + kb + t]);
                a[mf][2] = __float_as_uint(a_sm[r * 36 + kb + 4 + t]);
                a[mf][3] = __float_as_uint(a_sm[(r + 8) * 36 + kb + 4 + t]);
            }
            #pragma unroll
            for (int nf = 0; nf < 4; nf++) {
                int c = wn * 32 + nf * 8 + g;
                b[nf][0] = __float_as_uint(b_sm[(kb + t) * 136 + c]);
                b[nf][1] = __float_as_uint(b_sm[(kb + 4 + t) * 136 + c]);
            }
            #pragma unroll
            for (int mf = 0; mf < 2; mf++)
                #pragma unroll
                for (int nf = 0; nf < 4; nf++) mma8(acc[mf][nf], a[mf], b[nf]);
        }
    }

    #pragma unroll
    for (int mf = 0; mf < 2; mf++) {
        #pragma unroll
        for (int nf = 0; nf < 4; nf++) {
            int r0 = mbase + wm * 32 + mf * 16 + g;
            int cl = wn * 32 + nf * 8 + 2 * t;
            int c  = nbase + cl;
            float2 v0 = make_float2(acc[mf][nf][0] + bias_s[cl], acc[mf][nf][1] + bias_s[cl + 1]);
            float2 v1 = make_float2(acc[mf][nf][2] + bias_s[cl], acc[mf][nf][3] + bias_s[cl + 1]);
            *(float2*)(g_A + (size_t)r0 * 768 + c) = v0;
            *(float2*)(g_A + (size_t)(r0 + 8) * 768 + c) = v1;
        }
    }
}

// ---------------- gemm_small (output_sum): BM=64, BN=128, BK=32 ----------------
__global__ void __launch_bounds__(128) gemm_small(
    const float* __restrict__ A1, int lda1, const float* __restrict__ B1, int K1,
    const float* __restrict__ A2_, int lda2, const float* __restrict__ B2, int K2,
    int use_pd, const float* __restrict__ bias_, const float* __restrict__ addend,
    float* __restrict__ out_) {

    __shared__ float a_sm[64 * 36];
    __shared__ float b_sm[32 * 136];
    __shared__ float bias_s[128];

    const int tid   = threadIdx.x;
    const int nbase = blockIdx.x * 128;
    const int mbase = blockIdx.y * 64;
    const float* A2   = use_pd ? g_pd : A2_;
    float*       out  = out_ ? out_ : g_A;
    const float* bias = bias_ ? bias_ : g_bias_out;

    bias_s[tid] = bias[nbase + tid];

    const int w  = tid >> 5, lane = tid & 31;
    const int g  = lane >> 2, t = lane & 3;
    const int wm = w >> 1, wn = w & 1;

    float acc[2][8][4];
    #pragma unroll
    for (int mf = 0; mf < 2; mf++)
        #pragma unroll
        for (int nf = 0; nf < 8; nf++)
            #pragma unroll
            for (int q = 0; q < 4; q++) acc[mf][nf][q] = 0.f;

    #pragma unroll
    for (int s = 0; s < 2; s++) {
        const float* Ap = s ? A2 : A1;
        const float* Bp = s ? B2 : B1;
        const int lda   = s ? lda2 : lda1;
        const int Ks    = s ? K2 : K1;
        for (int kt = 0; kt < Ks; kt += 32) {
            #pragma unroll
            for (int it = 0; it < 4; it++) {
                int idx = tid + it * 128;
                int row = idx >> 3, k4 = idx & 7;
                float4 v = *(const float4*)(Ap + (size_t)(mbase + row) * lda + kt + k4 * 4);
                float4 wv = make_float4(to_tf32(v.x), to_tf32(v.y), to_tf32(v.z), to_tf32(v.w));
                *(float4*)(a_sm + row * 36 + k4 * 4) = wv;
            }
            #pragma unroll
            for (int it = 0; it < 8; it++) {
                int idx = tid + it * 128;
                int kr = idx >> 5, c4 = idx & 31;
                float4 v = *(const float4*)(Bp + (size_t)(kt + kr) * 768 + nbase + c4 * 4);
                float4 wv = make_float4(to_tf32(v.x), to_tf32(v.y), to_tf32(v.z), to_tf32(v.w));
                *(float4*)(b_sm + kr * 136 + c4 * 4) = wv;
            }
            __syncthreads();
            #pragma unroll
            for (int ks = 0; ks < 4; ks++) {
                const int kb = ks * 8;
                uint32_t a[2][4], b[8][2];
                #pragma unroll
                for (int mf = 0; mf < 2; mf++) {
                    int r = wm * 32 + mf * 16 + g;
                    a[mf][0] = __float_as_uint(a_sm[r * 36 + kb + t]);
                    a[mf][1] = __float_as_uint(a_sm[(r + 8) * 36 + kb + t]);
                    a[mf][2] = __float_as_uint(a_sm[r * 36 + kb + 4 + t]);
                    a[mf][3] = __float_as_uint(a_sm[(r + 8) * 36 + kb + 4 + t]);
                }
                #pragma unroll
                for (int nf = 0; nf < 8; nf++) {
                    int c = wn * 64 + nf * 8 + g;
                    b[nf][0] = __float_as_uint(b_sm[(kb + t) * 136 + c]);
                    b[nf][1] = __float_as_uint(b_sm[(kb + 4 + t) * 136 + c]);
                }
                #pragma unroll
                for (int mf = 0; mf < 2; mf++)
                    #pragma unroll
                    for (int nf = 0; nf < 8; nf++) mma8(acc[mf][nf], a[mf], b[nf]);
            }
            __syncthreads();
        }
    }

    #pragma unroll
    for (int mf = 0; mf < 2; mf++) {
        #pragma unroll
        for (int nf = 0; nf < 8; nf++) {
            int r0 = mbase + wm * 32 + mf * 16 + g;
            int cl = wn * 64 + nf * 8 + 2 * t;
            int c  = nbase + cl;
            float a0 = 0.f, a1 = 0.f, a2 = 0.f, a3 = 0.f;
            if (addend) {
                a0 = addend[(size_t)r0 * 768 + c];
                a1 = addend[(size_t)r0 * 768 + c + 1];
                a2 = addend[(size_t)(r0 + 8) * 768 + c];
                a3 = addend[(size_t)(r0 + 8) * 768 + c + 1];
            }
            float2 v0 = make_float2(acc[mf][nf][0] + bias_s[cl] + a0,
                                    acc[mf][nf][1] + bias_s[cl + 1] + a1);
            float2 v1 = make_float2(acc[mf][nf][2] + bias_s[cl] + a2,
                                    acc[mf][nf][3] + bias_s[cl + 1] + a3);
            *(float2*)(out + (size_t)r0 * 768 + c) = v0;
            *(float2*)(out + (size_t)(r0 + 8) * 768 + c) = v1;
        }
    }
}

// ---------------- kernel S: scores + softmax + p + p-weighted dep ----------------
__global__ void __launch_bounds__(128) kernel_s(
    const float* __restrict__ text, const int* __restrict__ adj,
    const float* __restrict__ dep, const float* __restrict__ pos,
    float* __restrict__ p_out) {

    __shared__ float dep_s[128 * 65];
    __shared__ float ws_s[64];
    __shared__ float p_s[128];
    __shared__ float red[128];

    const int bi  = blockIdx.x;
    const int tid = threadIdx.x;
    const int lane = tid & 31;

    if (tid < 64) ws_s[tid] = g_wd_sum[tid];

    float ps = 0.f;
    #pragma unroll
    for (int d = tid; d < 768; d += 128) ps += text[(size_t)bi * 768 + d] * g_wt_sum[d];
    if (tid < 64) ps += pos[(size_t)bi * 64 + tid] * g_wp_sum[tid];
    #pragma unroll
    for (int o = 16; o; o >>= 1) ps += __shfl_xor_sync(0xffffffffu, ps, o);
    if (lane == 0) red[tid >> 5] = ps;
    __syncthreads();
    const float s_base = red[0] + red[1] + red[2] + red[3] + g_bsum;
    __syncthreads();

    const float4* dr = (const float4*)(dep + ((size_t)bi * 128 + tid) * 64);
    float dot = 0.f;
    #pragma unroll
    for (int q = 0; q < 16; q++) {
        float4 v = dr[q];
        dot += v.x * ws_s[4 * q] + v.y * ws_s[4 * q + 1] + v.z * ws_s[4 * q + 2] + v.w * ws_s[4 * q + 3];
        int base = tid * 65 + 4 * q;
        dep_s[base]     = v.x;
        dep_s[base + 1] = v.y;
        dep_s[base + 2] = v.z;
        dep_s[base + 3] = v.w;
    }
    const float score = s_base + dot + (adj[(size_t)bi * 128 + tid] == 0 ? NEGC : 0.f);

    float m = score;
    #pragma unroll
    for (int o = 16; o; o >>= 1) m = fmaxf(m, __shfl_xor_sync(0xffffffffu, m, o));
    if (lane == 0) red[tid >> 5] = m;
    __syncthreads();
    const float mx = fmaxf(fmaxf(red[0], red[1]), fmaxf(red[2], red[3]));
    __syncthreads();
    const float e = expf(score - mx);
    float z = e;
    #pragma unroll
    for (int o = 16; o; o >>= 1) z += __shfl_xor_sync(0xffffffffu, z, o);
    if (lane == 0) red[tid >> 5] = z;
    __syncthreads();
    const float Z = red[0] + red[1] + red[2] + red[3];
    const float p = e / Z;
    p_s[tid] = p;
    p_out[(size_t)bi * 128 + tid] = p;
    __syncthreads();

    const int half = tid >> 6, k = tid & 63;
    float s = 0.f;
    #pragma unroll 4
    for (int j = half * 64; j < half * 64 + 64; j++) s += p_s[j] * dep_s[j * 65 + k];
    red[tid] = s;
    __syncthreads();
    if (tid < 64) g_pd[(size_t)bi * 64 + tid] = red[tid] + red[tid + 64];
}

// ---------------- kernel R: r = dep @ Wd_attn + A  (persistent; split-N stores) ----------------
constexpr int SD      = 68;                  // dep_s row stride (mod32==4)
constexpr int SBW     = 264;                 // wd_s row stride (mod32==8)
constexpr int R_DEPS  = 128 * SD;            // 8704 floats
constexpr int WDF     = 64 * SBW;            // 16896 floats
constexpr int R_SMEMB = (R_DEPS + WDF + 256) * 4;   // 103424 bytes
constexpr int NCH     = 49;

__global__ void __launch_bounds__(256, 1) kernel_r(
    const float* __restrict__ dep, const float* __restrict__ Wda,
    float* __restrict__ rout) {

    extern __shared__ float sm[];
    float* dep_s = sm;
    float* wd_s  = sm + R_DEPS;
    float* a_s   = wd_s + WDF;

    const int tid = threadIdx.x;
    const int nt  = blockIdx.x;   // 0..2 N-tile of 256 cols

    // ---- Wd_attn slice [64 x 256], column-permuted for STG.128 epilogue (once) ----
    #pragma unroll
    for (int it = 0; it < 16; it++) {
        int idx = tid + it * 256;
        int k = idx >> 6, c4 = idx & 63;
        float4 v = *(const float4*)(Wda + (size_t)k * 768 + nt * 256 + c4 * 4);
        int A  = c4 * 4;
        int L0 = (A & ~15) + (((A >> 2) & 3) << 1);
        *(float2*)(wd_s + k * SBW + L0)     = make_float2(to_tf32(v.x), to_tf32(v.y));
        *(float2*)(wd_s + k * SBW + L0 + 8) = make_float2(to_tf32(v.z), to_tf32(v.w));
    }

    const int w  = tid >> 5, lane = tid & 31;
    const int g  = lane >> 2, t = lane & 3;
    const int wm = w >> 2, wn = w & 3;   // 2 x 4 warps

    int bi = blockIdx.y;                 // strided by NCH

    float4 pf[8];
    float  pfa;
    {
        const float4* db4 = (const float4*)(dep + (size_t)bi * 8192);
        #pragma unroll
        for (int it = 0; it < 8; it++) pf[it] = db4[tid + it * 256];
        pfa = g_A[(size_t)bi * 768 + nt * 256 + tid];
    }

    while (true) {
        __syncthreads();
        #pragma unroll
        for (int it = 0; it < 8; it++) {
            int idx = tid + it * 256;
            int j = idx >> 4, k4 = idx & 15;
            float4 v = pf[it];
            *(float4*)(dep_s + j * SD + k4 * 4) =
                make_float4(to_tf32(v.x), to_tf32(v.y), to_tf32(v.z), to_tf32(v.w));
        }
        a_s[tid] = pfa;
        __syncthreads();

        const int bin = bi + NCH;
        if (bin < 1024) {
            const float4* db4 = (const float4*)(dep + (size_t)bin * 8192);
            #pragma unroll
            for (int it = 0; it < 8; it++) pf[it] = db4[tid + it * 256];
            pfa = g_A[(size_t)bin * 768 + nt * 256 + tid];
        }

        float* rbase = rout + (size_t)bi * 98304 + nt * 256;

        #pragma unroll
        for (int h = 0; h < 2; h++) {
            float acc[4][4][4];
            #pragma unroll
            for (int mf = 0; mf < 4; mf++)
                #pragma unroll
                for (int nf = 0; nf < 4; nf++)
                    #pragma unroll
                    for (int q = 0; q < 4; q++) acc[mf][nf][q] = 0.f;

            #pragma unroll
            for (int ks = 0; ks < 8; ks++) {
                const int kb = ks * 8;
                uint32_t a[4][4], b[4][2];
                #pragma unroll
                for (int mf = 0; mf < 4; mf++) {
                    int r = wm * 64 + mf * 16 + g;
                    a[mf][0] = __float_as_uint(dep_s[r * SD + kb + t]);
                    a[mf][1] = __float_as_uint(dep_s[(r + 8) * SD + kb + t]);
                    a[mf][2] = __float_as_uint(dep_s[r * SD + kb + 4 + t]);
                    a[mf][3] = __float_as_uint(dep_s[(r + 8) * SD + kb + 4 + t]);
                }
                #pragma unroll
                for (int nf = 0; nf < 4; nf++) {
                    int c = h * 128 + wn * 32 + nf * 8 + g;
                    b[nf][0] = __float_as_uint(wd_s[(kb + t) * SBW + c]);
                    b[nf][1] = __float_as_uint(wd_s[(kb + 4 + t) * SBW + c]);
                }
                #pragma unroll
                for (int mf = 0; mf < 4; mf++)
                    #pragma unroll
                    for (int nf = 0; nf < 4; nf++) mma8(acc[mf][nf], a[mf], b[nf]);
            }

            #pragma unroll
            for (int mf = 0; mf < 4; mf++) {
                #pragma unroll
                for (int q2 = 0; q2 < 2; q2++) {
                    int r0  = wm * 64 + mf * 16 + g;
                    int col = h * 128 + wn * 32 + (q2 << 4) + 4 * t;
                    float4 a4 = *(const float4*)(a_s + col);
                    float4 w0 = make_float4(acc[mf][2 * q2][0] + a4.x, acc[mf][2 * q2][1] + a4.y,
                                            acc[mf][2 * q2 + 1][0] + a4.z, acc[mf][2 * q2 + 1][1] + a4.w);
                    float4 w1 = make_float4(acc[mf][2 * q2][2] + a4.x, acc[mf][2 * q2][3] + a4.y,
                                            acc[mf][2 * q2 + 1][2] + a4.z, acc[mf][2 * q2 + 1][3] + a4.w);
                    __stcs((float4*)(rbase + (size_t)r0 * 768 + col), w0);
                    __stcs((float4*)(rbase + (size_t)(r0 + 8) * 768 + col), w1);
                }
            }
        }

        bi = bin;
        if (bi >= 1024) break;
    }
}

// ---------------- launch: plain serial, single stream, no events ----------------
extern "C" void kernel_launch(void* const* d_in, const int* in_sizes, int n_in,
                              void* d_out, int out_size) {
    const float* text = (const float*)d_in[0];
    const int*   adj  = (const int*)d_in[1];
    const float* dep  = (const float*)d_in[2];
    const float* pos  = (const float*)d_in[3];
    const float* Wt   = (const float*)d_in[4];
    const float* Wpa  = (const float*)d_in[5];
    const float* Wda  = (const float*)d_in[6];
    const float* ba   = (const float*)d_in[7];
    const float* Wd   = (const float*)d_in[8];
    const float* bd   = (const float*)d_in[9];
    const float* Wp   = (const float*)d_in[10];
    const float* bp   = (const float*)d_in[11];
    float* out = (float*)d_out;

    static bool init_done = false;
    if (!init_done) {
        cudaFuncSetAttribute(kernel_r, cudaFuncAttributeMaxDynamicSharedMemorySize, R_SMEMB);
        init_done = true;
    }

    // 1) row sums + combined bias (~3 us)
    k0_sums<<<116, 256>>>(Wt, Wpa, Wda, ba, bd, bp);
    // 2) A = text@Wt + pos@Wp_attn + b_attn -> g_A (pipelined, ~10-15 us)
    gemm_A<<<dim3(6, 16), 256>>>(text, pos, Wt, Wpa, ba);
    // 3) scores/softmax -> p (out), g_pd (~7 us)
    kernel_s<<<BI, 128>>>(text, adj, dep, pos, out + P_OFF);
    // 4) output_sum -> out[OS_OFF:) (independent of kernel_r; ~4 us)
    gemm_small<<<dim3(6, 16), 128>>>(pos, 64, Wp, 64, nullptr, 64, Wd, 64,
                                     /*use_pd=*/1, nullptr, text, out + OS_OFF);
    // 5) r = dep@Wd_attn + A -> out[0:R_SIZE)  — persistent kernel runs LAST,
    //    alone on the chip (R12 lesson: never co-schedule with the one-wave kernel)
    kernel_r<<<dim3(3, NCH), 256, R_SMEMB>>>(dep, Wda, out);
}

// round 17
// speedup vs baseline: 1.5739x; 1.1160x over previous
#include <cuda_runtime.h>
#include <cstdint>
#include <cstddef>

// ---------------- problem constants ----------------
constexpr int Bb   = 8;
constexpr int Ll   = 128;
constexpr int Dd   = 768;
constexpr int DEP  = 64;
constexpr int POSN = 64;
constexpr int OUTN = 768;
constexpr int BI   = Bb * Ll;                       // 1024 (b,i) rows
constexpr long long R_SIZE = (long long)BI * Ll * OUTN;   // 100663296
constexpr long long OS_OFF = R_SIZE;                       // output_sum offset
constexpr long long P_OFF  = R_SIZE + (long long)BI * OUTN; // p offset
#define NEGC (-1e30f)

// ---------------- scratch (device globals; no allocs) ----------------
__device__ __align__(16) float g_A[BI * OUTN];     // A[b,i,o]
__device__ __align__(16) float g_pd[BI * DEP];     // sum_j p * dep
__device__ float g_wt_sum[Dd];
__device__ float g_wp_sum[POSN];
__device__ float g_wd_sum[DEP];
__device__ float g_bias_out[OUTN];                 // bp + bd
__device__ float g_bsum;                           // sum(b_attn)

// ---------------- helpers ----------------
__device__ __forceinline__ float to_tf32(float x) {
    uint32_t u;
    asm("cvt.rna.tf32.f32 %0, %1;" : "=r"(u) : "f"(x));
    return __uint_as_float(u);
}
__device__ __forceinline__ void mma8(float c[4], const uint32_t a[4], const uint32_t b[2]) {
    asm volatile(
        "mma.sync.aligned.m16n8k8.row.col.f32.tf32.tf32.f32 "
        "{%0,%1,%2,%3},{%4,%5,%6,%7},{%8,%9},{%0,%1,%2,%3};\n"
        : "+f"(c[0]), "+f"(c[1]), "+f"(c[2]), "+f"(c[3])
        : "r"(a[0]), "r"(a[1]), "r"(a[2]), "r"(a[3]), "r"(b[0]), "r"(b[1]));
}

// ---------------- K0: row sums + combined bias (warp-per-row) ----------------
__global__ void k0_sums(const float* __restrict__ Wt, const float* __restrict__ Wpa,
                        const float* __restrict__ Wda, const float* __restrict__ b_attn,
                        const float* __restrict__ bd, const float* __restrict__ bp) {
    const int gw   = (blockIdx.x * blockDim.x + threadIdx.x) >> 5;
    const int lane = threadIdx.x & 31;
    if (gw <= 896) {
        const float* src;
        if (gw < 768)      src = Wt  + (size_t)gw * 768;
        else if (gw < 832) src = Wpa + (size_t)(gw - 768) * 768;
        else if (gw < 896) src = Wda + (size_t)(gw - 832) * 768;
        else               src = b_attn;
        const float4* p4 = (const float4*)src;
        float s = 0.f;
        #pragma unroll
        for (int i = 0; i < 6; i++) { float4 v = p4[lane + i * 32]; s += v.x + v.y + v.z + v.w; }
        #pragma unroll
        for (int o = 16; o; o >>= 1) s += __shfl_xor_sync(0xffffffffu, s, o);
        if (lane == 0) {
            if (gw < 768)      g_wt_sum[gw] = s;
            else if (gw < 832) g_wp_sum[gw - 768] = s;
            else if (gw < 896) g_wd_sum[gw - 832] = s;
            else               g_bsum = s;
        }
    } else if (gw >= 897 && gw < 921) {
        int n = (gw - 897) * 32 + lane;
        g_bias_out[n] = bp[n] + bd[n];
    }
}

// ---------------- k_fused: blocks 0..95 = gemm_A, blocks 96..1119 = kernel_s ----------------
// gemm_A: A = text@Wt + pos@Wpa + ba. BM=64, BN=128, BK=32, 256 thr (2x4 warps,
//         warp tile 32x32), register-prefetch double buffering. K order identical
//         to the original -> same A numerics.
// kernel_s: one (b,i) per block; original 128-thread semantics, threads 128..255 idle
//           through the barriers (same active-thread count per SM as before: smem-bound).
constexpr int FU_SMEMF = 8960;   // floats; >= max(gemm_A 6784, kernel_s 8640)

__global__ void __launch_bounds__(256) k_fused(
    const float* __restrict__ text, const float* __restrict__ pos,
    const float* __restrict__ Wt, const float* __restrict__ Wpa,
    const float* __restrict__ ba,
    const int* __restrict__ adj, const float* __restrict__ dep,
    float* __restrict__ p_out) {

    __shared__ float smem_u[FU_SMEMF];
    const int tid = threadIdx.x;

    if (blockIdx.x < 96) {
        // ================= gemm_A branch =================
        float* a_sm   = smem_u;                 // 64*36 = 2304
        float* b_sm   = smem_u + 2304;          // 32*136 = 4352
        float* bias_s = smem_u + 6656;          // 128

        const int bid   = blockIdx.x;
        const int nbase = (bid % 6) * 128;
        const int mbase = (bid / 6) * 64;

        if (tid < 128) bias_s[tid] = ba[nbase + tid];

        const int w  = tid >> 5, lane = tid & 31;
        const int g  = lane >> 2, t = lane & 3;
        const int wm = w >> 2, wn = w & 3;   // 2 x 4 warps

        float acc[2][4][4];
        #pragma unroll
        for (int mf = 0; mf < 2; mf++)
            #pragma unroll
            for (int nf = 0; nf < 4; nf++)
                #pragma unroll
                for (int q = 0; q < 4; q++) acc[mf][nf][q] = 0.f;

        float4 pfa[2], pfb[4];
        auto ldchunk = [&](int ch) {
            #pragma unroll
            for (int it = 0; it < 2; it++) {
                int idx = tid + it * 256;
                int row = idx >> 3, k4 = idx & 7;
                const float* src = (ch < 24)
                    ? text + (size_t)(mbase + row) * 768 + ch * 32 + k4 * 4
                    : pos  + (size_t)(mbase + row) * 64 + (ch - 24) * 32 + k4 * 4;
                pfa[it] = *(const float4*)src;
            }
            #pragma unroll
            for (int it = 0; it < 4; it++) {
                int idx = tid + it * 256;
                int kr = idx >> 5, c4 = idx & 31;
                const float* srcb = (ch < 24)
                    ? Wt  + (size_t)(ch * 32 + kr) * 768 + nbase + c4 * 4
                    : Wpa + (size_t)((ch - 24) * 32 + kr) * 768 + nbase + c4 * 4;
                pfb[it] = *(const float4*)srcb;
            }
        };
        ldchunk(0);

        for (int ch = 0; ch < 26; ch++) {
            __syncthreads();
            #pragma unroll
            for (int it = 0; it < 2; it++) {
                int idx = tid + it * 256;
                int row = idx >> 3, k4 = idx & 7;
                float4 v = pfa[it];
                *(float4*)(a_sm + row * 36 + k4 * 4) =
                    make_float4(to_tf32(v.x), to_tf32(v.y), to_tf32(v.z), to_tf32(v.w));
            }
            #pragma unroll
            for (int it = 0; it < 4; it++) {
                int idx = tid + it * 256;
                int kr = idx >> 5, c4 = idx & 31;
                float4 v = pfb[it];
                *(float4*)(b_sm + kr * 136 + c4 * 4) =
                    make_float4(to_tf32(v.x), to_tf32(v.y), to_tf32(v.z), to_tf32(v.w));
            }
            __syncthreads();
            if (ch + 1 < 26) ldchunk(ch + 1);

            #pragma unroll
            for (int ks = 0; ks < 4; ks++) {
                const int kb = ks * 8;
                uint32_t a[2][4], b[4][2];
                #pragma unroll
                for (int mf = 0; mf < 2; mf++) {
                    int r = wm * 32 + mf * 16 + g;
                    a[mf][0] = __float_as_uint(a_sm[r * 36 + kb + t]);
                    a[mf][1] = __float_as_uint(a_sm[(r + 8) * 36 + kb + t]);
                    a[mf][2] = __float_as_uint(a_sm[r * 36 + kb + 4 + t]);
                    a[mf][3] = __float_as_uint(a_sm[(r + 8) * 36 + kb + 4 + t]);
                }
                #pragma unroll
                for (int nf = 0; nf < 4; nf++) {
                    int c = wn * 32 + nf * 8 + g;
                    b[nf][0] = __float_as_uint(b_sm[(kb + t) * 136 + c]);
                    b[nf][1] = __float_as_uint(b_sm[(kb + 4 + t) * 136 + c]);
                }
                #pragma unroll
                for (int mf = 0; mf < 2; mf++)
                    #pragma unroll
                    for (int nf = 0; nf < 4; nf++) mma8(acc[mf][nf], a[mf], b[nf]);
            }
        }

        #pragma unroll
        for (int mf = 0; mf < 2; mf++) {
            #pragma unroll
            for (int nf = 0; nf < 4; nf++) {
                int r0 = mbase + wm * 32 + mf * 16 + g;
                int cl = wn * 32 + nf * 8 + 2 * t;
                int c  = nbase + cl;
                float2 v0 = make_float2(acc[mf][nf][0] + bias_s[cl], acc[mf][nf][1] + bias_s[cl + 1]);
                float2 v1 = make_float2(acc[mf][nf][2] + bias_s[cl], acc[mf][nf][3] + bias_s[cl + 1]);
                *(float2*)(g_A + (size_t)r0 * 768 + c) = v0;
                *(float2*)(g_A + (size_t)(r0 + 8) * 768 + c) = v1;
            }
        }
    } else {
        // ================= kernel_s branch (original 128-thread semantics) =================
        float* dep_s = smem_u;                 // 128*65 = 8320
        float* ws_s  = smem_u + 8320;          // 64
        float* p_s   = smem_u + 8384;          // 128
        float* red   = smem_u + 8512;          // 128

        const int bi   = blockIdx.x - 96;
        const int lane = tid & 31;
        const bool act = tid < 128;

        if (tid < 64) ws_s[tid] = g_wd_sum[tid];

        float ps = 0.f;
        if (act) {
            #pragma unroll
            for (int d = tid; d < 768; d += 128) ps += text[(size_t)bi * 768 + d] * g_wt_sum[d];
            if (tid < 64) ps += pos[(size_t)bi * 64 + tid] * g_wp_sum[tid];
            #pragma unroll
            for (int o = 16; o; o >>= 1) ps += __shfl_xor_sync(0xffffffffu, ps, o);
            if (lane == 0) red[tid >> 5] = ps;
        }
        __syncthreads();
        const float s_base = red[0] + red[1] + red[2] + red[3] + g_bsum;
        __syncthreads();

        float score = 0.f;
        if (act) {
            const float4* dr = (const float4*)(dep + ((size_t)bi * 128 + tid) * 64);
            float dot = 0.f;
            #pragma unroll
            for (int q = 0; q < 16; q++) {
                float4 v = dr[q];
                dot += v.x * ws_s[4 * q] + v.y * ws_s[4 * q + 1]
                     + v.z * ws_s[4 * q + 2] + v.w * ws_s[4 * q + 3];
                int base = tid * 65 + 4 * q;
                dep_s[base]     = v.x;
                dep_s[base + 1] = v.y;
                dep_s[base + 2] = v.z;
                dep_s[base + 3] = v.w;
            }
            score = s_base + dot + (adj[(size_t)bi * 128 + tid] == 0 ? NEGC : 0.f);

            float m = score;
            #pragma unroll
            for (int o = 16; o; o >>= 1) m = fmaxf(m, __shfl_xor_sync(0xffffffffu, m, o));
            if (lane == 0) red[tid >> 5] = m;
        }
        __syncthreads();
        const float mx = fmaxf(fmaxf(red[0], red[1]), fmaxf(red[2], red[3]));
        __syncthreads();

        float e = 0.f;
        if (act) {
            e = expf(score - mx);
            float z = e;
            #pragma unroll
            for (int o = 16; o; o >>= 1) z += __shfl_xor_sync(0xffffffffu, z, o);
            if (lane == 0) red[tid >> 5] = z;
        }
        __syncthreads();
        const float Z = red[0] + red[1] + red[2] + red[3];
        if (act) {
            const float p = e / Z;
            p_s[tid] = p;
            p_out[(size_t)bi * 128 + tid] = p;
        }
        __syncthreads();

        if (act) {
            const int half = tid >> 6, k = tid & 63;
            float s = 0.f;
            #pragma unroll 4
            for (int j = half * 64; j < half * 64 + 64; j++) s += p_s[j] * dep_s[j * 65 + k];
            red[tid] = s;
        }
        __syncthreads();
        if (tid < 64) g_pd[(size_t)bi * 64 + tid] = red[tid] + red[tid + 64];
    }
}

// ---------------- gemm_out: output_sum = pos@Wp + g_pd@Wd + (bp+bd) + text ----------------
// Pipelined like gemm_A: BM=64, BN=128, 4 K-chunks (pos 0..63 then pd 0..63),
// 256 thr (2x4 warps, warp tile 32x32), register-prefetch double buffering.
__global__ void __launch_bounds__(256) gemm_out(
    const float* __restrict__ pos, const float* __restrict__ Wp,
    const float* __restrict__ Wd, const float* __restrict__ text,
    float* __restrict__ out) {

    __shared__ float a_sm[64 * 36];
    __shared__ float b_sm[32 * 136];
    __shared__ float bias_s[128];

    const int tid   = threadIdx.x;
    const int nbase = blockIdx.x * 128;
    const int mbase = blockIdx.y * 64;

    if (tid < 128) bias_s[tid] = g_bias_out[nbase + tid];

    const int w  = tid >> 5, lane = tid & 31;
    const int g  = lane >> 2, t = lane & 3;
    const int wm = w >> 2, wn = w & 3;   // 2 x 4 warps

    float acc[2][4][4];
    #pragma unroll
    for (int mf = 0; mf < 2; mf++)
        #pragma unroll
        for (int nf = 0; nf < 4; nf++)
            #pragma unroll
            for (int q = 0; q < 4; q++) acc[mf][nf][q] = 0.f;

    float4 pfa[2], pfb[4];
    auto ldchunk = [&](int ch) {
        #pragma unroll
        for (int it = 0; it < 2; it++) {
            int idx = tid + it * 256;
            int row = idx >> 3, k4 = idx & 7;
            const float* src = (ch < 2)
                ? pos  + (size_t)(mbase + row) * 64 + ch * 32 + k4 * 4
                : g_pd + (size_t)(mbase + row) * 64 + (ch - 2) * 32 + k4 * 4;
            pfa[it] = *(const float4*)src;
        }
        #pragma unroll
        for (int it = 0; it < 4; it++) {
            int idx = tid + it * 256;
            int kr = idx >> 5, c4 = idx & 31;
            const float* srcb = (ch < 2)
                ? Wp + (size_t)(ch * 32 + kr) * 768 + nbase + c4 * 4
                : Wd + (size_t)((ch - 2) * 32 + kr) * 768 + nbase + c4 * 4;
            pfb[it] = *(const float4*)srcb;
        }
    };
    ldchunk(0);

    for (int ch = 0; ch < 4; ch++) {
        __syncthreads();
        #pragma unroll
        for (int it = 0; it < 2; it++) {
            int idx = tid + it * 256;
            int row = idx >> 3, k4 = idx & 7;
            float4 v = pfa[it];
            *(float4*)(a_sm + row * 36 + k4 * 4) =
                make_float4(to_tf32(v.x), to_tf32(v.y), to_tf32(v.z), to_tf32(v.w));
        }
        #pragma unroll
        for (int it = 0; it < 4; it++) {
            int idx = tid + it * 256;
            int kr = idx >> 5, c4 = idx & 31;
            float4 v = pfb[it];
            *(float4*)(b_sm + kr * 136 + c4 * 4) =
                make_float4(to_tf32(v.x), to_tf32(v.y), to_tf32(v.z), to_tf32(v.w));
        }
        __syncthreads();
        if (ch + 1 < 4) ldchunk(ch + 1);

        #pragma unroll
        for (int ks = 0; ks < 4; ks++) {
            const int kb = ks * 8;
            uint32_t a[2][4], b[4][2];
            #pragma unroll
            for (int mf = 0; mf < 2; mf++) {
                int r = wm * 32 + mf * 16 + g;
                a[mf][0] = __float_as_uint(a_sm[r * 36 + kb + t]);
                a[mf][1] = __float_as_uint(a_sm[(r + 8) * 36 + kb + t]);
                a[mf][2] = __float_as_uint(a_sm[r * 36 + kb + 4 + t]);
                a[mf][3] = __float_as_uint(a_sm[(r + 8) * 36 + kb + 4 + t]);
            }
            #pragma unroll
            for (int nf = 0; nf < 4; nf++) {
                int c = wn * 32 + nf * 8 + g;
                b[nf][0] = __float_as_uint(b_sm[(kb + t) * 136 + c]);
                b[nf][1] = __float_as_uint(b_sm[(kb + 4 + t) * 136 + c]);
            }
            #pragma unroll
            for (int mf = 0; mf < 2; mf++)
                #pragma unroll
                for (int nf = 0; nf < 4; nf++) mma8(acc[mf][nf], a[mf], b[nf]);
        }
    }

    #pragma unroll
    for (int mf = 0; mf < 2; mf++) {
        #pragma unroll
        for (int nf = 0; nf < 4; nf++) {
            int r0 = mbase + wm * 32 + mf * 16 + g;
            int cl = wn * 32 + nf * 8 + 2 * t;
            int c  = nbase + cl;
            float a0 = text[(size_t)r0 * 768 + c];
            float a1 = text[(size_t)r0 * 768 + c + 1];
            float a2 = text[(size_t)(r0 + 8) * 768 + c];
            float a3 = text[(size_t)(r0 + 8) * 768 + c + 1];
            float2 v0 = make_float2(acc[mf][nf][0] + bias_s[cl] + a0,
                                    acc[mf][nf][1] + bias_s[cl + 1] + a1);
            float2 v1 = make_float2(acc[mf][nf][2] + bias_s[cl] + a2,
                                    acc[mf][nf][3] + bias_s[cl + 1] + a3);
            *(float2*)(out + (size_t)r0 * 768 + c) = v0;
            *(float2*)(out + (size_t)(r0 + 8) * 768 + c) = v1;
        }
    }
}

// ---------------- kernel R: r = dep @ Wd_attn + A  (persistent; split-N stores) ----------------
constexpr int SD      = 68;                  // dep_s row stride (mod32==4)
constexpr int SBW     = 264;                 // wd_s row stride (mod32==8)
constexpr int R_DEPS  = 128 * SD;            // 8704 floats
constexpr int WDF     = 64 * SBW;            // 16896 floats
constexpr int R_SMEMB = (R_DEPS + WDF + 256) * 4;   // 103424 bytes
constexpr int NCH     = 49;

__global__ void __launch_bounds__(256, 1) kernel_r(
    const float* __restrict__ dep, const float* __restrict__ Wda,
    float* __restrict__ rout) {

    extern __shared__ float sm[];
    float* dep_s = sm;
    float* wd_s  = sm + R_DEPS;
    float* a_s   = wd_s + WDF;

    const int tid = threadIdx.x;
    const int nt  = blockIdx.x;   // 0..2 N-tile of 256 cols

    // ---- Wd_attn slice [64 x 256], column-permuted for STG.128 epilogue (once) ----
    #pragma unroll
    for (int it = 0; it < 16; it++) {
        int idx = tid + it * 256;
        int k = idx >> 6, c4 = idx & 63;
        float4 v = *(const float4*)(Wda + (size_t)k * 768 + nt * 256 + c4 * 4);
        int A  = c4 * 4;
        int L0 = (A & ~15) + (((A >> 2) & 3) << 1);
        *(float2*)(wd_s + k * SBW + L0)     = make_float2(to_tf32(v.x), to_tf32(v.y));
        *(float2*)(wd_s + k * SBW + L0 + 8) = make_float2(to_tf32(v.z), to_tf32(v.w));
    }

    const int w  = tid >> 5, lane = tid & 31;
    const int g  = lane >> 2, t = lane & 3;
    const int wm = w >> 2, wn = w & 3;   // 2 x 4 warps

    int bi = blockIdx.y;                 // strided by NCH

    float4 pf[8];
    float  pfa;
    {
        const float4* db4 = (const float4*)(dep + (size_t)bi * 8192);
        #pragma unroll
        for (int it = 0; it < 8; it++) pf[it] = db4[tid + it * 256];
        pfa = g_A[(size_t)bi * 768 + nt * 256 + tid];
    }

    while (true) {
        __syncthreads();
        #pragma unroll
        for (int it = 0; it < 8; it++) {
            int idx = tid + it * 256;
            int j = idx >> 4, k4 = idx & 15;
            float4 v = pf[it];
            *(float4*)(dep_s + j * SD + k4 * 4) =
                make_float4(to_tf32(v.x), to_tf32(v.y), to_tf32(v.z), to_tf32(v.w));
        }
        a_s[tid] = pfa;
        __syncthreads();

        const int bin = bi + NCH;
        if (bin < 1024) {
            const float4* db4 = (const float4*)(dep + (size_t)bin * 8192);
            #pragma unroll
            for (int it = 0; it < 8; it++) pf[it] = db4[tid + it * 256];
            pfa = g_A[(size_t)bin * 768 + nt * 256 + tid];
        }

        float* rbase = rout + (size_t)bi * 98304 + nt * 256;

        #pragma unroll
        for (int h = 0; h < 2; h++) {
            float acc[4][4][4];
            #pragma unroll
            for (int mf = 0; mf < 4; mf++)
                #pragma unroll
                for (int nf = 0; nf < 4; nf++)
                    #pragma unroll
                    for (int q = 0; q < 4; q++) acc[mf][nf][q] = 0.f;

            #pragma unroll
            for (int ks = 0; ks < 8; ks++) {
                const int kb = ks * 8;
                uint32_t a[4][4], b[4][2];
                #pragma unroll
                for (int mf = 0; mf < 4; mf++) {
                    int r = wm * 64 + mf * 16 + g;
                    a[mf][0] = __float_as_uint(dep_s[r * SD + kb + t]);
                    a[mf][1] = __float_as_uint(dep_s[(r + 8) * SD + kb + t]);
                    a[mf][2] = __float_as_uint(dep_s[r * SD + kb + 4 + t]);
                    a[mf][3] = __float_as_uint(dep_s[(r + 8) * SD + kb + 4 + t]);
                }
                #pragma unroll
                for (int nf = 0; nf < 4; nf++) {
                    int c = h * 128 + wn * 32 + nf * 8 + g;
                    b[nf][0] = __float_as_uint(wd_s[(kb + t) * SBW + c]);
                    b[nf][1] = __float_as_uint(wd_s[(kb + 4 + t) * SBW + c]);
                }
                #pragma unroll
                for (int mf = 0; mf < 4; mf++)
                    #pragma unroll
                    for (int nf = 0; nf < 4; nf++) mma8(acc[mf][nf], a[mf], b[nf]);
            }

            #pragma unroll
            for (int mf = 0; mf < 4; mf++) {
                #pragma unroll
                for (int q2 = 0; q2 < 2; q2++) {
                    int r0  = wm * 64 + mf * 16 + g;
                    int col = h * 128 + wn * 32 + (q2 << 4) + 4 * t;
                    float4 a4 = *(const float4*)(a_s + col);
                    float4 w0 = make_float4(acc[mf][2 * q2][0] + a4.x, acc[mf][2 * q2][1] + a4.y,
                                            acc[mf][2 * q2 + 1][0] + a4.z, acc[mf][2 * q2 + 1][1] + a4.w);
                    float4 w1 = make_float4(acc[mf][2 * q2][2] + a4.x, acc[mf][2 * q2][3] + a4.y,
                                            acc[mf][2 * q2 + 1][2] + a4.z, acc[mf][2 * q2 + 1][3] + a4.w);
                    __stcs((float4*)(rbase + (size_t)r0 * 768 + col), w0);
                    __stcs((float4*)(rbase + (size_t)(r0 + 8) * 768 + col), w1);
                }
            }
        }

        bi = bin;
        if (bi >= 1024) break;
    }
}

// ---------------- launch: plain serial, single stream ----------------
extern "C" void kernel_launch(void* const* d_in, const int* in_sizes, int n_in,
                              void* d_out, int out_size) {
    const float* text = (const float*)d_in[0];
    const int*   adj  = (const int*)d_in[1];
    const float* dep  = (const float*)d_in[2];
    const float* pos  = (const float*)d_in[3];
    const float* Wt   = (const float*)d_in[4];
    const float* Wpa  = (const float*)d_in[5];
    const float* Wda  = (const float*)d_in[6];
    const float* ba   = (const float*)d_in[7];
    const float* Wd   = (const float*)d_in[8];
    const float* bd   = (const float*)d_in[9];
    const float* Wp   = (const float*)d_in[10];
    const float* bp   = (const float*)d_in[11];
    float* out = (float*)d_out;

    static bool init_done = false;
    if (!init_done) {
        cudaFuncSetAttribute(kernel_r, cudaFuncAttributeMaxDynamicSharedMemorySize, R_SMEMB);
        init_done = true;
    }

    // 1) row sums + combined bias (~3 us)
    k0_sums<<<116, 256>>>(Wt, Wpa, Wda, ba, bd, bp);
    // 2) fused: gemm_A (blocks 0..95) + kernel_s (blocks 96..1119), overlapped (~15 us)
    k_fused<<<1120, 256>>>(text, pos, Wt, Wpa, ba, adj, dep, out + P_OFF);
    // 3) output_sum -> out[OS_OFF:), pipelined (~6 us)
    gemm_out<<<dim3(6, 16), 256>>>(pos, Wp, Wd, text, out + OS_OFF);
    // 4) r = dep@Wd_attn + A -> out[0:R_SIZE) — persistent kernel LAST, alone on chip
    kernel_r<<<dim3(3, NCH), 256, R_SMEMB>>>(dep, Wda, out);
}